// round 4
// baseline (speedup 1.0000x reference)
#include <cuda_runtime.h>

#define BATCH 32
#define TSEQ  1024
#define DIN   256
#define UNITS 256
#define GC    2048   // 8*U total gate columns
#define G4    1024   // 4*U per direction

// ---------------- scratch (device globals; no runtime allocation) ------------
// xg layout: [t][col 0..2047][b]  (col = dir*1024 + gate*256 + unit)
__device__ float g_xg[TSEQ * GC * BATCH];            // 256 MB
__device__ float g_hist[TSEQ * 512 * BATCH];         // h history [t][dir*256+u][b], 64 MB
__device__ unsigned int g_arrive[2][64];             // per-CTA arrival slots

// ---- PTX helpers -------------------------------------------------------------
#define CP_ASYNC16(dst_u32, src_ptr) \
    asm volatile("cp.async.cg.shared.global [%0], [%1], 16;" :: "r"(dst_u32), "l"(src_ptr))
#define CP_COMMIT() asm volatile("cp.async.commit_group;" ::: "memory")
#define CP_WAIT(n)  asm volatile("cp.async.wait_group %0;" :: "n"(n) : "memory")

__device__ __forceinline__ unsigned smem_u32(const void* p) {
    unsigned a;
    asm("{ .reg .u64 t; cvta.to.shared.u64 t, %1; cvt.u32.u64 %0, t; }" : "=r"(a) : "l"(p));
    return a;
}
__device__ __forceinline__ float fast_tanh(float x) {
    float r;
    asm("tanh.approx.f32 %0, %1;" : "=f"(r) : "f"(x));
    return r;
}

// ---------------- input projection GEMM: xg = x @ kernel ---------------------
// M = 32768 rows (r = t*32 + b), N = 2048, K = 256. Tiles 128x128x16.
// Inner product uses packed fma.rn.f32x2 (FFMA2): 32 packed FMAs + 8 dup-movs
// per k instead of 64 scalar FFMAs.
__global__ void __launch_bounds__(256, 2) gemm_xg(const float* __restrict__ x,
                                                  const float* __restrict__ Wk) {
    __shared__ float As[16][132];   // [k][m], padded
    __shared__ float Bs[16][128];   // [k][n]

    const int tid = threadIdx.x;
    // reset rec barrier slots for this launch (rec runs after gemm completes)
    if (blockIdx.x == 0 && blockIdx.y == 0 && tid < 128)
        ((unsigned*)g_arrive)[tid] = 0u;

    const int tx = tid & 15;        // n micro index
    const int ty = tid >> 4;        // m micro index
    const int n0 = blockIdx.x * 128;
    const int t0 = blockIdx.y * 4;  // 4 time steps * 32 batch = 128 rows

    unsigned long long acc2[8][4];  // acc2[i][jq] = {acc[i][2jq], acc[i][2jq+1]}
#pragma unroll
    for (int i = 0; i < 8; i++)
#pragma unroll
        for (int j = 0; j < 4; j++) acc2[i][j] = 0ull;

    for (int k0 = 0; k0 < DIN; k0 += 16) {
#pragma unroll
        for (int r = 0; r < 2; r++) {
            int idx = tid * 2 + r;              // 0..511
            int mloc = idx >> 2;                // 0..127
            int kq = idx & 3;
            int b = mloc & 31, tloc = mloc >> 5;
            float4 v = *(const float4*)&x[b * (TSEQ * DIN) + (t0 + tloc) * DIN + k0 + kq * 4];
            As[kq * 4 + 0][mloc] = v.x;
            As[kq * 4 + 1][mloc] = v.y;
            As[kq * 4 + 2][mloc] = v.z;
            As[kq * 4 + 3][mloc] = v.w;
        }
#pragma unroll
        for (int r = 0; r < 2; r++) {
            int idx = tid * 2 + r;              // 0..511
            int kk = idx >> 5;                  // 0..15
            int cq = idx & 31;
            *(float4*)&Bs[kk][cq * 4] = *(const float4*)&Wk[(k0 + kk) * GC + n0 + cq * 4];
        }
        __syncthreads();
#pragma unroll
        for (int k = 0; k < 16; k++) {
            float a[8];
            *(float4*)&a[0] = *(const float4*)&As[k][ty * 8];
            *(float4*)&a[4] = *(const float4*)&As[k][ty * 8 + 4];
            ulonglong2 bb0 = *(const ulonglong2*)&Bs[k][tx * 8];
            ulonglong2 bb1 = *(const ulonglong2*)&Bs[k][tx * 8 + 4];
            unsigned long long bv0 = bb0.x, bv1 = bb0.y, bv2 = bb1.x, bv3 = bb1.y;
#pragma unroll
            for (int i = 0; i < 8; i++) {
                unsigned long long a2;
                asm("mov.b64 %0, {%1, %1};" : "=l"(a2) : "f"(a[i]));
                asm("fma.rn.f32x2 %0, %1, %2, %0;" : "+l"(acc2[i][0]) : "l"(a2), "l"(bv0));
                asm("fma.rn.f32x2 %0, %1, %2, %0;" : "+l"(acc2[i][1]) : "l"(a2), "l"(bv1));
                asm("fma.rn.f32x2 %0, %1, %2, %0;" : "+l"(acc2[i][2]) : "l"(a2), "l"(bv2));
                asm("fma.rn.f32x2 %0, %1, %2, %0;" : "+l"(acc2[i][3]) : "l"(a2), "l"(bv3));
            }
        }
        __syncthreads();
    }
#pragma unroll
    for (int i = 0; i < 8; i++) {
        int mloc = ty * 8 + i;
        int b = mloc & 31, tloc = mloc >> 5;
        int t = t0 + tloc;
        float* orow = &g_xg[((size_t)t * GC + n0 + tx * 8) * BATCH + b];
#pragma unroll
        for (int jq = 0; jq < 4; jq++) {
            float lo, hi;
            asm("mov.b64 {%0, %1}, %2;" : "=f"(lo), "=f"(hi) : "l"(acc2[i][jq]));
            orow[(size_t)(2 * jq + 0) * BATCH] = lo;
            orow[(size_t)(2 * jq + 1) * BATCH] = hi;
        }
    }
}

// ---------------- persistent recurrent scan ----------------------------------
// 128 CTAs (64 per direction), 256 threads (8 warps) each. CTA owns 4 units.
// warp w: wu = w&3 -> unit offset, kh = w>>2 -> k-half. lane = batch.
// Grid barrier: per-CTA distinct arrival slots (no atomic serialization),
// 64 threads poll the 64 contiguous words.
__global__ void __launch_bounds__(256, 1) blstm_rec(const float* __restrict__ rk) {
    __shared__ float Ws[UNITS * 16];      // [k][wu*4+g] : 16 KB
    __shared__ float hs[UNITS * BATCH];   // [k][b]      : 32 KB (total 48 KB)
    // reduction partials scribble over the first 2 KB of hs (consumed before
    // next step's staging overwrites hs).
    ulonglong2* red_s = (ulonglong2*)hs;

    const int tid  = threadIdx.x;
    const int lane = tid & 31;            // batch b
    const int w    = tid >> 5;            // warp 0..7
    const int wu   = w & 3;               // unit offset 0..3
    const int kh   = w >> 2;              // k-half 0/1
    const int dir  = blockIdx.x >> 6;
    const int cta  = blockIdx.x & 63;
    const int u0   = cta * 4;
    const int u    = u0 + wu;

    // Ws[k*16 + wu*4 + g] = rk[k][dir*1024 + g*256 + u0+wu]
    for (int i = tid; i < UNITS * 16; i += 256) {
        int k = i >> 4, c = i & 15;
        int cu = c >> 2, g = c & 3;
        Ws[i] = rk[k * GC + dir * G4 + g * UNITS + u0 + cu];
    }
    for (int i = tid; i < (UNITS * BATCH) / 4; i += 256)
        ((float4*)hs)[i] = make_float4(0.f, 0.f, 0.f, 0.f);
    __syncthreads();

    const unsigned hs_base = smem_u32(hs);
    const ulonglong2* Ws2 = (const ulonglong2*)Ws;
    unsigned int* my_slot   = &g_arrive[dir][cta];
    unsigned int* poll_slot = &g_arrive[dir][tid & 63];
    float c_state = 0.f;
    int tprev = 0;

    for (int s = 0; s < TSEQ; s++) {
        const int t = dir ? (TSEQ - 1 - s) : s;

        // gate-bias DRAM loads first (consumed ~1500 cyc later)
        float bi, bf, bm, bo;
        if (kh == 0) {
            const float* xgp = &g_xg[((size_t)t * GC + dir * G4) * BATCH];
            bi = __ldcs(&xgp[(0 * UNITS + u) * BATCH + lane]);
            bf = __ldcs(&xgp[(1 * UNITS + u) * BATCH + lane]);
            bm = __ldcs(&xgp[(2 * UNITS + u) * BATCH + lane]);
            bo = __ldcs(&xgp[(3 * UNITS + u) * BATCH + lane]);
        }

        // stage h_{s-1} from g_hist into smem (all 256 threads, 8 x 16B each)
        if (s > 0) {
            const float* src = &g_hist[((size_t)tprev * 512 + dir * 256) * BATCH];
#pragma unroll
            for (int j = 0; j < 8; j++)
                CP_ASYNC16(hs_base + (unsigned)(tid + j * 256) * 16u, src + (tid + j * 256) * 4);
            CP_COMMIT();
            CP_WAIT(0);
            __syncthreads();
        }

        // half-dot: k in [kh*128, kh*128+128)
        unsigned long long aif = 0ull, amo = 0ull;   // packed (i,f),(m,o) fp32x2
        const int kbase = kh << 7;
#pragma unroll 8
        for (int k = 0; k < 128; k++) {
            ulonglong2 wv = Ws2[(kbase + k) * 4 + wu];   // broadcast LDS.128
            float hv = hs[(kbase + k) * 32 + lane];      // conflict-free LDS.32
            unsigned long long h2;
            asm("mov.b64 %0, {%1, %1};" : "=l"(h2) : "f"(hv));
            asm("fma.rn.f32x2 %0, %1, %2, %0;" : "+l"(aif) : "l"(wv.x), "l"(h2));
            asm("fma.rn.f32x2 %0, %1, %2, %0;" : "+l"(amo) : "l"(wv.y), "l"(h2));
        }
        __syncthreads();            // everyone done reading hs
        if (kh == 1) {
            red_s[wu * 32 + lane] = make_ulonglong2(aif, amo);
        }
        __syncthreads();

        if (kh == 0) {
            ulonglong2 p = red_s[wu * 32 + lane];
            asm("add.rn.f32x2 %0, %0, %1;" : "+l"(aif) : "l"(p.x));
            asm("add.rn.f32x2 %0, %0, %1;" : "+l"(amo) : "l"(p.y));
            float ai, af, am, ao;
            asm("mov.b64 {%0, %1}, %2;" : "=f"(ai), "=f"(af) : "l"(aif));
            asm("mov.b64 {%0, %1}, %2;" : "=f"(am), "=f"(ao) : "l"(amo));
            ai += bi; af += bf; am += bm; ao += bo;

            float gi = __saturatef(0.2f * ai + 0.5f);
            float gf = __saturatef(0.2f * af + 0.5f);
            float gm = fast_tanh(am);
            float go = __saturatef(0.2f * ao + 0.5f);
            c_state = gf * c_state + gi * gm;
            float h = go * fast_tanh(c_state);

            g_hist[((size_t)t * 512 + dir * 256 + u) * BATCH + lane] = h;   // coalesced
        }

        // ---- per-direction grid barrier (distinct slots, no atomics) ----
        __syncthreads();    // h stores (all threads) ordered before the release
        if (tid == 0)
            asm volatile("st.release.gpu.global.u32 [%0], %1;"
                         :: "l"(my_slot), "r"((unsigned)(s + 1)) : "memory");
        if (tid < 64) {
            const unsigned target = (unsigned)(s + 1);
            unsigned v;
            do {
                asm volatile("ld.acquire.gpu.global.u32 %0, [%1];"
                             : "=r"(v) : "l"(poll_slot) : "memory");
            } while (v < target);
        }
        __syncthreads();
        tprev = t;
    }
}

// ---------------- final transpose: out[b][t][c] = hist[t][c][b] --------------
__global__ void __launch_bounds__(256) transpose_out(float* __restrict__ out) {
    __shared__ float S[128 * 33];
    const int t  = blockIdx.x;        // 0..1023
    const int c0 = blockIdx.y * 128;  // 0..3 * 128
    const int tid = threadIdx.x;

    const float* src = &g_hist[((size_t)t * 512 + c0) * BATCH];
#pragma unroll
    for (int i = 0; i < 4; i++) {
        int idx4 = tid + i * 256;                 // 0..1023 float4s
        float4 v = ((const float4*)src)[idx4];
        int e = idx4 * 4;
        int c = e >> 5, b0 = e & 31;
        float* d = &S[c * 33 + b0];
        d[0] = v.x; d[1] = v.y; d[2] = v.z; d[3] = v.w;
    }
    __syncthreads();

    const int lane = tid & 31;   // c quad index
    const int bq   = tid >> 5;   // 0..7
#pragma unroll
    for (int i = 0; i < 4; i++) {
        int b = bq + i * 8;
        int cc = lane * 4;
        float4 v = make_float4(S[(cc + 0) * 33 + b], S[(cc + 1) * 33 + b],
                               S[(cc + 2) * 33 + b], S[(cc + 3) * 33 + b]);
        *(float4*)&out[((size_t)b * TSEQ + t) * 512 + c0 + cc] = v;
    }
}

// ---------------- entry ------------------------------------------------------
extern "C" void kernel_launch(void* const* d_in, const int* in_sizes, int n_in,
                              void* d_out, int out_size) {
    (void)in_sizes; (void)n_in; (void)out_size;
    const float* x    = (const float*)d_in[0];   // [32,1024,256]
    const float* kern = (const float*)d_in[1];   // [256,2048]
    const float* rk   = (const float*)d_in[2];   // [256,2048]
    float* out = (float*)d_out;                  // [32,1024,512]

    dim3 ggrid(GC / 128, (BATCH * TSEQ) / 128);  // (16, 256)
    gemm_xg<<<ggrid, 256>>>(x, kern);
    blstm_rec<<<128, 256>>>(rk);
    dim3 tgrid(TSEQ, 4);
    transpose_out<<<tgrid, 256>>>(out);
}

// round 5
// speedup vs baseline: 2.1152x; 2.1152x over previous
#include <cuda_runtime.h>

#define BATCH 32
#define TSEQ  1024
#define DIN   256
#define UNITS 256
#define GC    2048   // 8*U total gate columns
#define G4    1024   // 4*U per direction

// ---------------- scratch (device globals; no runtime allocation) ------------
// xg layout: [t][col 0..2047][b]  (col = dir*1024 + gate*256 + unit)
__device__ float g_xg[TSEQ * GC * BATCH];            // 256 MB
__device__ float g_hist[TSEQ * 512 * BATCH];         // h history [t][dir*256+u][b], 64 MB
__device__ unsigned int g_cnt[64];                   // per-direction barrier counters (padded)

// ---- PTX helpers -------------------------------------------------------------
#define CP_ASYNC16(dst_u32, src_ptr) \
    asm volatile("cp.async.cg.shared.global [%0], [%1], 16;" :: "r"(dst_u32), "l"(src_ptr))
#define CP_COMMIT() asm volatile("cp.async.commit_group;" ::: "memory")
#define CP_WAIT(n)  asm volatile("cp.async.wait_group %0;" :: "n"(n) : "memory")

__device__ __forceinline__ unsigned smem_u32(const void* p) {
    unsigned a;
    asm("{ .reg .u64 t; cvta.to.shared.u64 t, %1; cvt.u32.u64 %0, t; }" : "=r"(a) : "l"(p));
    return a;
}
__device__ __forceinline__ float fast_tanh(float x) {
    float r;
    asm("tanh.approx.f32 %0, %1;" : "=f"(r) : "f"(x));
    return r;
}

// ---------------- input projection GEMM: xg = x @ kernel ---------------------
// M = 32768 rows (r = t*32 + b), N = 2048, K = 256. Tiles 128x128x16.
__global__ void __launch_bounds__(256, 2) gemm_xg(const float* __restrict__ x,
                                                  const float* __restrict__ Wk) {
    __shared__ float As[16][132];   // [k][m], padded
    __shared__ float Bs[16][128];   // [k][n]

    const int tid = threadIdx.x;
    // reset rec barrier counters for this launch (rec runs after gemm completes)
    if (blockIdx.x == 0 && blockIdx.y == 0 && tid < 64) g_cnt[tid] = 0u;

    const int tx = tid & 15;        // n micro index
    const int ty = tid >> 4;        // m micro index
    const int n0 = blockIdx.x * 128;
    const int t0 = blockIdx.y * 4;  // 4 time steps * 32 batch = 128 rows

    unsigned long long acc2[8][4];  // acc2[i][jq] = {acc[i][2jq], acc[i][2jq+1]}
#pragma unroll
    for (int i = 0; i < 8; i++)
#pragma unroll
        for (int j = 0; j < 4; j++) acc2[i][j] = 0ull;

    for (int k0 = 0; k0 < DIN; k0 += 16) {
#pragma unroll
        for (int r = 0; r < 2; r++) {
            int idx = tid * 2 + r;              // 0..511
            int mloc = idx >> 2;                // 0..127
            int kq = idx & 3;
            int b = mloc & 31, tloc = mloc >> 5;
            float4 v = *(const float4*)&x[b * (TSEQ * DIN) + (t0 + tloc) * DIN + k0 + kq * 4];
            As[kq * 4 + 0][mloc] = v.x;
            As[kq * 4 + 1][mloc] = v.y;
            As[kq * 4 + 2][mloc] = v.z;
            As[kq * 4 + 3][mloc] = v.w;
        }
#pragma unroll
        for (int r = 0; r < 2; r++) {
            int idx = tid * 2 + r;              // 0..511
            int kk = idx >> 5;                  // 0..15
            int cq = idx & 31;
            *(float4*)&Bs[kk][cq * 4] = *(const float4*)&Wk[(k0 + kk) * GC + n0 + cq * 4];
        }
        __syncthreads();
#pragma unroll
        for (int k = 0; k < 16; k++) {
            float a[8];
            *(float4*)&a[0] = *(const float4*)&As[k][ty * 8];
            *(float4*)&a[4] = *(const float4*)&As[k][ty * 8 + 4];
            ulonglong2 bb0 = *(const ulonglong2*)&Bs[k][tx * 8];
            ulonglong2 bb1 = *(const ulonglong2*)&Bs[k][tx * 8 + 4];
            unsigned long long bv0 = bb0.x, bv1 = bb0.y, bv2 = bb1.x, bv3 = bb1.y;
#pragma unroll
            for (int i = 0; i < 8; i++) {
                unsigned long long a2;
                asm("mov.b64 %0, {%1, %1};" : "=l"(a2) : "f"(a[i]));
                asm("fma.rn.f32x2 %0, %1, %2, %0;" : "+l"(acc2[i][0]) : "l"(a2), "l"(bv0));
                asm("fma.rn.f32x2 %0, %1, %2, %0;" : "+l"(acc2[i][1]) : "l"(a2), "l"(bv1));
                asm("fma.rn.f32x2 %0, %1, %2, %0;" : "+l"(acc2[i][2]) : "l"(a2), "l"(bv2));
                asm("fma.rn.f32x2 %0, %1, %2, %0;" : "+l"(acc2[i][3]) : "l"(a2), "l"(bv3));
            }
        }
        __syncthreads();
    }
#pragma unroll
    for (int i = 0; i < 8; i++) {
        int mloc = ty * 8 + i;
        int b = mloc & 31, tloc = mloc >> 5;
        int t = t0 + tloc;
        float* orow = &g_xg[((size_t)t * GC + n0 + tx * 8) * BATCH + b];
#pragma unroll
        for (int jq = 0; jq < 4; jq++) {
            float lo, hi;
            asm("mov.b64 {%0, %1}, %2;" : "=f"(lo), "=f"(hi) : "l"(acc2[i][jq]));
            orow[(size_t)(2 * jq + 0) * BATCH] = lo;
            orow[(size_t)(2 * jq + 1) * BATCH] = hi;
        }
    }
}

// ---------------- persistent recurrent scan ----------------------------------
// 128 CTAs (64 per direction), 256 threads (8 warps) each. CTA owns 4 units.
// warp w: wu = w&3 -> unit offset, kh = w>>2 -> k-half. lane = batch.
// Each kh-group (4 warps, 128 threads) stages its own 16KB k-half and syncs on
// its own named barrier, so neither group waits for the other's staging.
__global__ void __launch_bounds__(256, 1) blstm_rec(const float* __restrict__ rk) {
    __shared__ float Ws[UNITS * 16];      // [k][wu*4+g] : 16 KB
    __shared__ float hs[UNITS * BATCH];   // [k][b]      : 32 KB (total 48 KB)
    // reduction partials alias hs[0..255] (k=0..7 region; consumed before the
    // next step's kh=0 staging overwrites it — ordered by the grid barrier).
    ulonglong2* red_s = (ulonglong2*)hs;

    const int tid  = threadIdx.x;
    const int lane = tid & 31;            // batch b
    const int w    = tid >> 5;            // warp 0..7
    const int wu   = w & 3;               // unit offset 0..3
    const int kh   = w >> 2;              // k-half 0/1
    const int gtid = tid & 127;           // thread id within kh-group
    const int dir  = blockIdx.x >> 6;
    const int cta  = blockIdx.x & 63;
    const int u0   = cta * 4;
    const int u    = u0 + wu;

    // Ws[k*16 + wu*4 + g] = rk[k][dir*1024 + g*256 + u0+wu]
    for (int i = tid; i < UNITS * 16; i += 256) {
        int k = i >> 4, c = i & 15;
        int cu = c >> 2, g = c & 3;
        Ws[i] = rk[k * GC + dir * G4 + g * UNITS + u0 + cu];
    }
    for (int i = tid; i < (UNITS * BATCH) / 4; i += 256)
        ((float4*)hs)[i] = make_float4(0.f, 0.f, 0.f, 0.f);
    __syncthreads();

    const unsigned hs_base = smem_u32(hs);
    const ulonglong2* Ws2 = (const ulonglong2*)Ws;
    unsigned int* cnt = &g_cnt[dir * 32];
    float c_state = 0.f;
    int tprev = 0;

    for (int s = 0; s < TSEQ; s++) {
        const int t = dir ? (TSEQ - 1 - s) : s;

        // gate-bias DRAM loads first (consumed ~2000 cyc later)
        float bi, bf, bm, bo;
        if (kh == 0) {
            const float* xgp = &g_xg[((size_t)t * GC + dir * G4) * BATCH];
            bi = __ldcs(&xgp[(0 * UNITS + u) * BATCH + lane]);
            bf = __ldcs(&xgp[(1 * UNITS + u) * BATCH + lane]);
            bm = __ldcs(&xgp[(2 * UNITS + u) * BATCH + lane]);
            bo = __ldcs(&xgp[(3 * UNITS + u) * BATCH + lane]);
        }

        // stage h_{s-1}: each kh-group stages its own 16KB half (8 x 16B/thread)
        if (s > 0) {
            const float* src = &g_hist[((size_t)tprev * 512 + dir * 256) * BATCH] + (kh << 12);
            const unsigned dst0 = hs_base + ((unsigned)kh << 14);
#pragma unroll
            for (int j = 0; j < 8; j++)
                CP_ASYNC16(dst0 + (unsigned)(gtid + j * 128) * 16u, src + (gtid + j * 128) * 4);
            CP_COMMIT();
            CP_WAIT(0);
            // group barrier: warps 0-3 on bar 1, warps 4-7 on bar 2
            asm volatile("bar.sync %0, 128;" :: "r"(1 + kh) : "memory");
        }

        // half-dot: k in [kh*128, kh*128+128)
        unsigned long long aif = 0ull, amo = 0ull;   // packed (i,f),(m,o) fp32x2
        const int kbase = kh << 7;
#pragma unroll 8
        for (int k = 0; k < 128; k++) {
            ulonglong2 wv = Ws2[(kbase + k) * 4 + wu];   // broadcast LDS.128
            float hv = hs[(kbase + k) * 32 + lane];      // conflict-free LDS.32
            unsigned long long h2;
            asm("mov.b64 %0, {%1, %1};" : "=l"(h2) : "f"(hv));
            asm("fma.rn.f32x2 %0, %1, %2, %0;" : "+l"(aif) : "l"(wv.x), "l"(h2));
            asm("fma.rn.f32x2 %0, %1, %2, %0;" : "+l"(amo) : "l"(wv.y), "l"(h2));
        }
        __syncthreads();            // all warps done reading hs
        if (kh == 1) {
            red_s[wu * 32 + lane] = make_ulonglong2(aif, amo);
        }
        __syncthreads();

        if (kh == 0) {
            ulonglong2 p = red_s[wu * 32 + lane];
            asm("add.rn.f32x2 %0, %0, %1;" : "+l"(aif) : "l"(p.x));
            asm("add.rn.f32x2 %0, %0, %1;" : "+l"(amo) : "l"(p.y));
            float ai, af, am, ao;
            asm("mov.b64 {%0, %1}, %2;" : "=f"(ai), "=f"(af) : "l"(aif));
            asm("mov.b64 {%0, %1}, %2;" : "=f"(am), "=f"(ao) : "l"(amo));
            ai += bi; af += bf; am += bm; ao += bo;

            float gi = __saturatef(0.2f * ai + 0.5f);
            float gf = __saturatef(0.2f * af + 0.5f);
            float gm = fast_tanh(am);
            float go = __saturatef(0.2f * ao + 0.5f);
            c_state = gf * c_state + gi * gm;
            float h = go * fast_tanh(c_state);

            g_hist[((size_t)t * 512 + dir * 256 + u) * BATCH + lane] = h;   // coalesced
        }

        // ---- per-direction grid barrier: red.release arrive, 1 poller/CTA with
        // nanosleep backoff (minimal L2 poll traffic) ----
        __syncthreads();    // h stores happen-before tid0's release (cumulative)
        if (tid == 0) {
            asm volatile("red.release.gpu.global.add.u32 [%0], 1;" :: "l"(cnt) : "memory");
            const unsigned target = (unsigned)(s + 1) * 64u;
            unsigned v;
            asm volatile("ld.acquire.gpu.global.u32 %0, [%1];" : "=r"(v) : "l"(cnt) : "memory");
            while (v < target) {
                __nanosleep(32);
                asm volatile("ld.acquire.gpu.global.u32 %0, [%1];" : "=r"(v) : "l"(cnt) : "memory");
            }
        }
        __syncthreads();
        tprev = t;
    }
}

// ---------------- final transpose: out[b][t][c] = hist[t][c][b] --------------
__global__ void __launch_bounds__(256) transpose_out(float* __restrict__ out) {
    __shared__ float S[128 * 33];
    const int t  = blockIdx.x;        // 0..1023
    const int c0 = blockIdx.y * 128;  // 0..3 * 128
    const int tid = threadIdx.x;

    const float* src = &g_hist[((size_t)t * 512 + c0) * BATCH];
#pragma unroll
    for (int i = 0; i < 4; i++) {
        int idx4 = tid + i * 256;                 // 0..1023 float4s
        float4 v = ((const float4*)src)[idx4];
        int e = idx4 * 4;
        int c = e >> 5, b0 = e & 31;
        float* d = &S[c * 33 + b0];
        d[0] = v.x; d[1] = v.y; d[2] = v.z; d[3] = v.w;
    }
    __syncthreads();

    const int lane = tid & 31;   // c quad index
    const int bq   = tid >> 5;   // 0..7
#pragma unroll
    for (int i = 0; i < 4; i++) {
        int b = bq + i * 8;
        int cc = lane * 4;
        float4 v = make_float4(S[(cc + 0) * 33 + b], S[(cc + 1) * 33 + b],
                               S[(cc + 2) * 33 + b], S[(cc + 3) * 33 + b]);
        *(float4*)&out[((size_t)b * TSEQ + t) * 512 + c0 + cc] = v;
    }
}

// ---------------- entry ------------------------------------------------------
extern "C" void kernel_launch(void* const* d_in, const int* in_sizes, int n_in,
                              void* d_out, int out_size) {
    (void)in_sizes; (void)n_in; (void)out_size;
    const float* x    = (const float*)d_in[0];   // [32,1024,256]
    const float* kern = (const float*)d_in[1];   // [256,2048]
    const float* rk   = (const float*)d_in[2];   // [256,2048]
    float* out = (float*)d_out;                  // [32,1024,512]

    dim3 ggrid(GC / 128, (BATCH * TSEQ) / 128);  // (16, 256)
    gemm_xg<<<ggrid, 256>>>(x, kern);
    blstm_rec<<<128, 256>>>(rk);
    dim3 tgrid(TSEQ, 4);
    transpose_out<<<tgrid, 256>>>(out);
}